// round 6
// baseline (speedup 1.0000x reference)
#include <cuda_runtime.h>
#include <cuda_bf16.h>
#include <math.h>
#include <stdint.h>

#define DIM   768
#define HEADS 12
#define HD    64
#define WIN   14
#define NTOK  196
#define NWIN  50
#define MROWS 9800
#define GROWS 8192
#define MLPH  3072
#define QKVN  2304
#define SCALE 0.125f

// -------------------- scratch (device globals; no allocation) ----------------
__device__ float g_xin_ln[MROWS * DIM];
__device__ float g_qkv  [MROWS * QKVN];
__device__ float g_attn [MROWS * DIM];
__device__ float g_xres [GROWS * DIM];
__device__ float g_h2   [GROWS * DIM];
__device__ float g_hid  [GROWS * MLPH];

// -------------------- helpers ------------------------------------------------
__device__ __forceinline__ void cp16(float* dst, const float* src) {
    uint32_t d = (uint32_t)__cvta_generic_to_shared(dst);
    asm volatile("cp.async.cg.shared.global [%0], [%1], 16;\n" :: "r"(d), "l"(src));
}
#define CP_COMMIT()  asm volatile("cp.async.commit_group;\n")
#define CP_WAIT1()   asm volatile("cp.async.wait_group 1;\n")

__device__ __forceinline__ uint32_t tf32u(float x) {
    uint32_t r;
    asm("cvt.rna.tf32.f32 %0, %1;" : "=r"(r) : "f"(x));
    return r;
}

__device__ __forceinline__ void blockReduce2(float& s, float& ss) {
    #pragma unroll
    for (int o = 16; o; o >>= 1) {
        s  += __shfl_xor_sync(0xffffffffu, s,  o);
        ss += __shfl_xor_sync(0xffffffffu, ss, o);
    }
    __shared__ float ra[8], rb[8];
    int warp = threadIdx.x >> 5, lane = threadIdx.x & 31;
    if (lane == 0) { ra[warp] = s; rb[warp] = ss; }
    __syncthreads();
    if (threadIdx.x == 0) {
        float t1 = 0.f, t2 = 0.f;
        #pragma unroll
        for (int i = 0; i < 8; i++) { t1 += ra[i]; t2 += rb[i]; }
        ra[0] = t1; rb[0] = t2;
    }
    __syncthreads();
    s = ra[0]; ss = rb[0];
}

// -------------------- LN1 + window partition (zero pad) ----------------------
__global__ __launch_bounds__(256) void ln1_kernel(
    const float* __restrict__ x, const float* __restrict__ g,
    const float* __restrict__ b, float* __restrict__ out)
{
    int t = blockIdx.x;
    int w  = t / NTOK, tk = t % NTOK;
    int img = w / 25, wy = (w % 25) / 5, wx = w % 5;
    int ty = tk / WIN, tx = tk % WIN;
    int y = wy * WIN + ty, xc = wx * WIN + tx;
    float* orow = out + (size_t)t * DIM;
    int tid = threadIdx.x;
    if (y >= 64 || xc >= 64) {
        orow[tid] = 0.f; orow[tid + 256] = 0.f; orow[tid + 512] = 0.f;
        return;
    }
    const float* row = x + (((size_t)img * 64 + y) * 64 + xc) * DIM;
    float v0 = row[tid], v1 = row[tid + 256], v2 = row[tid + 512];
    float s = v0 + v1 + v2, ss = v0 * v0 + v1 * v1 + v2 * v2;
    blockReduce2(s, ss);
    float mean = s * (1.f / DIM);
    float var  = ss * (1.f / DIM) - mean * mean;
    float rstd = rsqrtf(var + 1e-6f);
    orow[tid]       = (v0 - mean) * rstd * g[tid]       + b[tid];
    orow[tid + 256] = (v1 - mean) * rstd * g[tid + 256] + b[tid + 256];
    orow[tid + 512] = (v2 - mean) * rstd * g[tid + 512] + b[tid + 512];
}

__global__ __launch_bounds__(256) void ln2_kernel(
    const float* __restrict__ xin, const float* __restrict__ g,
    const float* __restrict__ b, float* __restrict__ out)
{
    int t = blockIdx.x;
    const float* row = xin + (size_t)t * DIM;
    float* orow = out + (size_t)t * DIM;
    int tid = threadIdx.x;
    float v0 = row[tid], v1 = row[tid + 256], v2 = row[tid + 512];
    float s = v0 + v1 + v2, ss = v0 * v0 + v1 * v1 + v2 * v2;
    blockReduce2(s, ss);
    float mean = s * (1.f / DIM);
    float var  = ss * (1.f / DIM) - mean * mean;
    float rstd = rsqrtf(var + 1e-6f);
    orow[tid]       = (v0 - mean) * rstd * g[tid]       + b[tid];
    orow[tid + 256] = (v1 - mean) * rstd * g[tid + 256] + b[tid + 256];
    orow[tid + 512] = (v2 - mean) * rstd * g[tid + 512] + b[tid + 512];
}

// -------------------- tf32 tensor-core GEMM, k=32 tiles, 3-stage cp.async ----
// 128x128 CTA tile, 8 warps (64x32 each), m16n8k8 tf32 mma, fragment
// double-buffering across the 4 k-halves of each 32-deep tile.
#define BSTR 136                 // Bs row stride (floats)
#define ASTAGE_F (128 * 32)      // A stage floats (swizzled, pad-free)
#define BSTAGE_F (32 * BSTR)     // B stage floats
#define STAGES 3
#define GEMM_SMEM_BYTES (STAGES * (ASTAGE_F + BSTAGE_F) * 4)

template<bool GATHER, bool GELU_ACT, bool RES>
__global__ __launch_bounds__(256, 2) void gemm_tc(
    const float* __restrict__ A, const float* __restrict__ B,
    const float* __restrict__ bias, const float* __restrict__ Rs,
    float* __restrict__ C, int M, int Nn, int K)
{
    extern __shared__ float smem[];
    float* smA = smem;
    float* smB = smem + STAGES * ASTAGE_F;

    const int tid  = threadIdx.x;
    const int lane = tid & 31;
    const int warp = tid >> 5;
    const int wm = warp >> 2;
    const int wn = warp & 3;
    const int bm = blockIdx.y << 7;
    const int bn = blockIdx.x << 7;

    // ---- global->smem load assignments ----
    const int am   = tid >> 1;           // 0..127 (A row)
    const int ak16 = (tid & 1) << 4;     // 0 or 16
    int gm = bm + am;
    int arow = gm < M ? gm : M - 1;
    if (GATHER) {
        int img = arow >> 12, rem = arow & 4095;
        int y = rem >> 6, xc = rem & 63;
        arow = (img * 25 + (y / WIN) * 5 + (xc / WIN)) * NTOK
             + (y % WIN) * WIN + (xc % WIN);
    }
    const float* aptr = A + (size_t)arow * K + ak16;
    // swizzled A dst offsets (4 groups of 4 floats)
    int agrp[4];
    #pragma unroll
    for (int i = 0; i < 4; i++) {
        int g = (ak16 >> 2) + i;
        int gx = (g + (am & 7)) & 7;
        agrp[i] = am * 32 + 4 * gx;
    }
    const int bkr = tid >> 3;            // 0..31 (B k-row)
    const int nb  = (tid & 7) << 4;      // 0..112
    const float* bptr = B + (size_t)bkr * Nn + bn + nb;
    const int bdst = bkr * BSTR + nb;

    const int KT = K >> 5;               // k-tiles of 32

    // ---- fragment addressing ----
    uint32_t sA0 = (uint32_t)__cvta_generic_to_shared(smA);
    const int mrow_off = (wm * 64 + (lane & 15)) * 32;   // floats
    const int lswz = lane & 7;
    const int bfr  = (lane & 3) * BSTR + wn * 32 + (lane >> 2);

    float acc[4][4][4];
    #pragma unroll
    for (int i = 0; i < 4; i++)
        #pragma unroll
        for (int j = 0; j < 4; j++)
            #pragma unroll
            for (int c = 0; c < 4; c++) acc[i][j][c] = 0.f;

    // ---- issue helper ----
    auto issue = [&](int kt, int s) {
        const float* ap = aptr + kt * 32;
        float* Abase = smA + s * ASTAGE_F;
        cp16(Abase + agrp[0], ap);
        cp16(Abase + agrp[1], ap + 4);
        cp16(Abase + agrp[2], ap + 8);
        cp16(Abase + agrp[3], ap + 12);
        const float* bp = bptr + (size_t)kt * 32 * Nn;
        float* bd = smB + s * BSTAGE_F + bdst;
        cp16(bd,      bp);
        cp16(bd + 4,  bp + 4);
        cp16(bd + 8,  bp + 8);
        cp16(bd + 12, bp + 12);
    };

    // ---- fragment buffers ----
    uint32_t fa[2][4][4];
    uint32_t fb0[2][4], fb1[2][4];

    auto loadA = [&](int buf, int kh, uint32_t sAc) {
        int gx = (((lane >> 4) + kh * 2) + lswz) & 7;
        uint32_t base = sAc + 4u * (mrow_off + 4 * gx);
        #pragma unroll
        for (int mt = 0; mt < 4; mt++) {
            uint32_t addr = base + (uint32_t)(mt * (16 * 32 * 4));
            asm volatile("ldmatrix.sync.aligned.m8n8.x4.shared.b16 {%0,%1,%2,%3}, [%4];"
                : "=r"(fa[buf][mt][0]), "=r"(fa[buf][mt][1]),
                  "=r"(fa[buf][mt][2]), "=r"(fa[buf][mt][3])
                : "r"(addr));
            #pragma unroll
            for (int c = 0; c < 4; c++)
                fa[buf][mt][c] = tf32u(__uint_as_float(fa[buf][mt][c]));
        }
    };
    auto loadB = [&](int buf, int kh, const float* Bc) {
        const float* bq = Bc + kh * 8 * BSTR + bfr;
        #pragma unroll
        for (int nt = 0; nt < 4; nt++) {
            fb0[buf][nt] = tf32u(bq[nt * 8]);
            fb1[buf][nt] = tf32u(bq[4 * BSTR + nt * 8]);
        }
    };

    // ---- prologue: stages 0,1 ----
    issue(0, 0); CP_COMMIT();
    issue(1, 1); CP_COMMIT();

    int cs = 0, is = 2;
    for (int kt = 0; kt < KT; kt++) {
        CP_WAIT1();
        __syncthreads();
        if (kt + 2 < KT) issue(kt + 2, is);
        CP_COMMIT();
        is = (is + 1 == STAGES) ? 0 : is + 1;

        uint32_t sAc = sA0 + (uint32_t)(cs * ASTAGE_F * 4);
        const float* Bc = smB + cs * BSTAGE_F;

        loadA(0, 0, sAc);
        loadB(0, 0, Bc);
        #pragma unroll
        for (int kh = 0; kh < 4; kh++) {
            int cb = kh & 1, nx = cb ^ 1;
            if (kh < 3) { loadA(nx, kh + 1, sAc); loadB(nx, kh + 1, Bc); }
            #pragma unroll
            for (int mt = 0; mt < 4; mt++)
                #pragma unroll
                for (int nt = 0; nt < 4; nt++) {
                    asm volatile(
                        "mma.sync.aligned.m16n8k8.row.col.f32.tf32.tf32.f32 "
                        "{%0,%1,%2,%3}, {%4,%5,%6,%7}, {%8,%9}, {%0,%1,%2,%3};"
                        : "+f"(acc[mt][nt][0]), "+f"(acc[mt][nt][1]),
                          "+f"(acc[mt][nt][2]), "+f"(acc[mt][nt][3])
                        : "r"(fa[cb][mt][0]), "r"(fa[cb][mt][1]),
                          "r"(fa[cb][mt][2]), "r"(fa[cb][mt][3]),
                          "r"(fb0[cb][nt]), "r"(fb1[cb][nt]));
                }
        }
        cs = (cs + 1 == STAGES) ? 0 : cs + 1;
    }

    // ---- epilogue ----
    const int rbase = bm + wm * 64 + (lane >> 2);
    const int cbase = bn + wn * 32 + (lane & 3) * 2;
    #pragma unroll
    for (int nt = 0; nt < 4; nt++) {
        int col = cbase + nt * 8;
        float bs0 = bias[col], bs1 = bias[col + 1];
        #pragma unroll
        for (int mt = 0; mt < 4; mt++) {
            int r0 = rbase + mt * 16;
            int r1 = r0 + 8;
            float v00 = acc[mt][nt][0] + bs0;
            float v01 = acc[mt][nt][1] + bs1;
            float v10 = acc[mt][nt][2] + bs0;
            float v11 = acc[mt][nt][3] + bs1;
            if (GELU_ACT) {
                v00 = 0.5f * v00 * (1.f + erff(v00 * 0.70710678f));
                v01 = 0.5f * v01 * (1.f + erff(v01 * 0.70710678f));
                v10 = 0.5f * v10 * (1.f + erff(v10 * 0.70710678f));
                v11 = 0.5f * v11 * (1.f + erff(v11 * 0.70710678f));
            }
            if (r0 < M) {
                if (RES) {
                    const float* rr = Rs + (size_t)r0 * Nn + col;
                    v00 += rr[0]; v01 += rr[1];
                }
                *(float2*)(C + (size_t)r0 * Nn + col) = make_float2(v00, v01);
            }
            if (r1 < M) {
                if (RES) {
                    const float* rr = Rs + (size_t)r1 * Nn + col;
                    v10 += rr[0]; v11 += rr[1];
                }
                *(float2*)(C + (size_t)r1 * Nn + col) = make_float2(v10, v11);
            }
        }
    }
}

// -------------------- attention: one CTA per (window, head) ------------------
#define KV_STRIDE 68
#define SM_K   0
#define SM_V   (NTOK * KV_STRIDE)
#define SM_P   (2 * NTOK * KV_STRIDE)
#define SM_R   (SM_P + 8 * NTOK)
#define ATTN_SMEM_FLOATS (SM_R + 8 * 28)

__global__ __launch_bounds__(256) void attn_kernel(
    const float* __restrict__ qkv, const float* __restrict__ relh,
    const float* __restrict__ relw, float* __restrict__ outp)
{
    extern __shared__ float sm[];
    float* Ks = sm + SM_K;
    float* Vs = sm + SM_V;

    const int blk = blockIdx.x;
    const int w = blk / HEADS, h = blk % HEADS;
    const float* base = qkv + (size_t)w * NTOK * QKVN;
    const int tid = threadIdx.x, warp = tid >> 5, lane = tid & 31;

    for (int idx = tid; idx < NTOK * HD; idx += 256) {
        int j = idx >> 6, d = idx & 63;
        const float* src = base + (size_t)j * QKVN + h * HD + d;
        Ks[j * KV_STRIDE + d] = src[DIM];
        Vs[j * KV_STRIDE + d] = src[2 * DIM];
    }
    __syncthreads();

    float* myp  = sm + SM_P + warp * NTOK;
    float* myrh = sm + SM_R + warp * 28;
    float* myrw = myrh + 14;

    for (int r = warp; r < NTOK; r += 8) {
        const float4* qsrc = (const float4*)(base + (size_t)r * QKVN + h * HD);
        float4 qv[16];
        #pragma unroll
        for (int d4 = 0; d4 < 16; d4++) qv[d4] = qsrc[d4];

        int ty = r / WIN, tx = r % WIN;
        if (lane < 28) {
            int kk = lane % 14;
            bool isw = lane >= 14;
            const float4* rp = (const float4*)(isw ? (relw + (size_t)(tx - kk + 13) * HD)
                                                   : (relh + (size_t)(ty - kk + 13) * HD));
            float s = 0.f;
            #pragma unroll
            for (int d4 = 0; d4 < 16; d4++) {
                float4 rv = rp[d4];
                s += qv[d4].x * rv.x + qv[d4].y * rv.y + qv[d4].z * rv.z + qv[d4].w * rv.w;
            }
            (isw ? myrw : myrh)[kk] = s;
        }
        __syncwarp();

        float sc[7];
        float mx = -INFINITY;
        #pragma unroll
        for (int i = 0; i < 7; i++) {
            int j = lane + i * 32;
            float s = -INFINITY;
            if (j < NTOK) {
                const float4* kr = (const float4*)(Ks + j * KV_STRIDE);
                float a = 0.f;
                #pragma unroll
                for (int d4 = 0; d4 < 16; d4++) {
                    float4 kv = kr[d4];
                    a += qv[d4].x * kv.x + qv[d4].y * kv.y + qv[d4].z * kv.z + qv[d4].w * kv.w;
                }
                s = a * SCALE + myrh[j / WIN] + myrw[j % WIN];
            }
            sc[i] = s;
            mx = fmaxf(mx, s);
        }
        #pragma unroll
        for (int o = 16; o; o >>= 1) mx = fmaxf(mx, __shfl_xor_sync(0xffffffffu, mx, o));
        float sum = 0.f;
        #pragma unroll
        for (int i = 0; i < 7; i++) {
            int j = lane + i * 32;
            if (j < NTOK) {
                float e = __expf(sc[i] - mx);
                sum += e;
                myp[j] = e;
            }
        }
        #pragma unroll
        for (int o = 16; o; o >>= 1) sum += __shfl_xor_sync(0xffffffffu, sum, o);
        float inv = 1.f / sum;
        __syncwarp();

        float2 acc = make_float2(0.f, 0.f);
        #pragma unroll 4
        for (int j = 0; j < NTOK; j++) {
            float p = myp[j];
            float2 vv = *(const float2*)(Vs + j * KV_STRIDE + lane * 2);
            acc.x += p * vv.x;
            acc.y += p * vv.y;
        }
        float* orow = outp + ((size_t)w * NTOK + r) * DIM + h * HD;
        *(float2*)(orow + lane * 2) = make_float2(acc.x * inv, acc.y * inv);
        __syncwarp();
    }
}

// -------------------- launch -------------------------------------------------
extern "C" void kernel_launch(void* const* d_in, const int* in_sizes, int n_in,
                              void* d_out, int out_size)
{
    const float* x      = (const float*)d_in[0];
    const float* ln1_g  = (const float*)d_in[1];
    const float* ln1_b  = (const float*)d_in[2];
    const float* qkv_w  = (const float*)d_in[3];
    const float* qkv_b  = (const float*)d_in[4];
    const float* proj_w = (const float*)d_in[5];
    const float* proj_b = (const float*)d_in[6];
    const float* rel_h  = (const float*)d_in[7];
    const float* rel_w  = (const float*)d_in[8];
    const float* ln2_g  = (const float*)d_in[9];
    const float* ln2_b  = (const float*)d_in[10];
    const float* fc1_w  = (const float*)d_in[11];
    const float* fc1_b  = (const float*)d_in[12];
    const float* fc2_w  = (const float*)d_in[13];
    const float* fc2_b  = (const float*)d_in[14];
    float* out = (float*)d_out;

    float *p_xin, *p_qkv, *p_attn, *p_xres, *p_h2, *p_hid;
    cudaGetSymbolAddress((void**)&p_xin,  g_xin_ln);
    cudaGetSymbolAddress((void**)&p_qkv,  g_qkv);
    cudaGetSymbolAddress((void**)&p_attn, g_attn);
    cudaGetSymbolAddress((void**)&p_xres, g_xres);
    cudaGetSymbolAddress((void**)&p_h2,   g_h2);
    cudaGetSymbolAddress((void**)&p_hid,  g_hid);

    const int attn_smem = ATTN_SMEM_FLOATS * sizeof(float);
    cudaFuncSetAttribute(attn_kernel, cudaFuncAttributeMaxDynamicSharedMemorySize, attn_smem);
    cudaFuncSetAttribute((const void*)gemm_tc<false, false, false>,
                         cudaFuncAttributeMaxDynamicSharedMemorySize, GEMM_SMEM_BYTES);
    cudaFuncSetAttribute((const void*)gemm_tc<true, false, true>,
                         cudaFuncAttributeMaxDynamicSharedMemorySize, GEMM_SMEM_BYTES);
    cudaFuncSetAttribute((const void*)gemm_tc<false, true, false>,
                         cudaFuncAttributeMaxDynamicSharedMemorySize, GEMM_SMEM_BYTES);
    cudaFuncSetAttribute((const void*)gemm_tc<false, false, true>,
                         cudaFuncAttributeMaxDynamicSharedMemorySize, GEMM_SMEM_BYTES);

    // 1. LN1 + window partition
    ln1_kernel<<<MROWS, 256>>>(x, ln1_g, ln1_b, p_xin);

    // 2. QKV GEMM [9800,768]x[768,2304]
    gemm_tc<false, false, false><<<dim3(QKVN / 128, (MROWS + 127) / 128), 256, GEMM_SMEM_BYTES>>>(
        p_xin, qkv_w, qkv_b, nullptr, p_qkv, MROWS, QKVN, DIM);

    // 3. attention
    attn_kernel<<<NWIN * HEADS, 256, attn_smem>>>(p_qkv, rel_h, rel_w, p_attn);

    // 4. proj GEMM + gather + residual
    gemm_tc<true, false, true><<<dim3(DIM / 128, GROWS / 128), 256, GEMM_SMEM_BYTES>>>(
        p_attn, proj_w, proj_b, x, p_xres, GROWS, DIM, DIM);

    // 5. LN2
    ln2_kernel<<<GROWS, 256>>>(p_xres, ln2_g, ln2_b, p_h2);

    // 6. fc1 + GELU
    gemm_tc<false, true, false><<<dim3(MLPH / 128, GROWS / 128), 256, GEMM_SMEM_BYTES>>>(
        p_h2, fc1_w, fc1_b, nullptr, p_hid, GROWS, MLPH, DIM);

    // 7. fc2 + residual -> out
    gemm_tc<false, false, true><<<dim3(DIM / 128, GROWS / 128), 256, GEMM_SMEM_BYTES>>>(
        p_hid, fc2_w, fc2_b, p_xres, out, GROWS, DIM, MLPH);
}

// round 10
// speedup vs baseline: 1.5237x; 1.5237x over previous
#include <cuda_runtime.h>
#include <cuda_fp16.h>
#include <math.h>
#include <stdint.h>

#define DIM   768
#define HEADS 12
#define HD    64
#define WIN   14
#define NTOK  196
#define NWIN  50
#define MROWS 9800
#define GROWS 8192
#define MLPH  3072
#define QKVN  2304
#define SCALE 0.125f

// -------------------- scratch (device globals; no allocation) ----------------
__device__ __half g_xin_h [MROWS * DIM];    // LN1 out (half), window-partitioned
__device__ float  g_qkv   [MROWS * QKVN];   // qkv fp32 (softmax path wants fp32)
__device__ __half g_attn_h[MROWS * DIM];    // attention out (half)
__device__ float  g_xres  [GROWS * DIM];    // x + proj (fp32 master)
__device__ __half g_h2_h  [GROWS * DIM];    // LN2 out (half)
__device__ __half g_hid_h [GROWS * MLPH];   // gelu(fc1) (half)
// transposed half weights, rebuilt every launch
__device__ __half g_qkvwT [QKVN * DIM];
__device__ __half g_projwT[DIM * DIM];
__device__ __half g_fc1wT [MLPH * DIM];
__device__ __half g_fc2wT [DIM * MLPH];

// -------------------- helpers ------------------------------------------------
__device__ __forceinline__ void cp16(void* dst, const void* src) {
    uint32_t d = (uint32_t)__cvta_generic_to_shared(dst);
    asm volatile("cp.async.cg.shared.global [%0], [%1], 16;\n" :: "r"(d), "l"(src));
}
#define CP_COMMIT()  asm volatile("cp.async.commit_group;\n")
#define CP_WAIT2()   asm volatile("cp.async.wait_group 2;\n")

__device__ __forceinline__ void blockReduce2(float& s, float& ss) {
    #pragma unroll
    for (int o = 16; o; o >>= 1) {
        s  += __shfl_xor_sync(0xffffffffu, s,  o);
        ss += __shfl_xor_sync(0xffffffffu, ss, o);
    }
    __shared__ float ra[8], rb[8];
    int warp = threadIdx.x >> 5, lane = threadIdx.x & 31;
    if (lane == 0) { ra[warp] = s; rb[warp] = ss; }
    __syncthreads();
    if (threadIdx.x == 0) {
        float t1 = 0.f, t2 = 0.f;
        #pragma unroll
        for (int i = 0; i < 8; i++) { t1 += ra[i]; t2 += rb[i]; }
        ra[0] = t1; rb[0] = t2;
    }
    __syncthreads();
    s = ra[0]; ss = rb[0];
}

// -------------------- LN1 + window partition (half out) ----------------------
__global__ __launch_bounds__(256) void ln1_kernel(
    const float* __restrict__ x, const float* __restrict__ g,
    const float* __restrict__ b, __half* __restrict__ out)
{
    int t = blockIdx.x;
    int w  = t / NTOK, tk = t % NTOK;
    int img = w / 25, wy = (w % 25) / 5, wx = w % 5;
    int ty = tk / WIN, tx = tk % WIN;
    int y = wy * WIN + ty, xc = wx * WIN + tx;
    __half* orow = out + (size_t)t * DIM;
    int tid = threadIdx.x;
    if (y >= 64 || xc >= 64) {
        orow[tid] = __float2half(0.f);
        orow[tid + 256] = __float2half(0.f);
        orow[tid + 512] = __float2half(0.f);
        return;
    }
    const float* row = x + (((size_t)img * 64 + y) * 64 + xc) * DIM;
    float v0 = row[tid], v1 = row[tid + 256], v2 = row[tid + 512];
    float s = v0 + v1 + v2, ss = v0 * v0 + v1 * v1 + v2 * v2;
    blockReduce2(s, ss);
    float mean = s * (1.f / DIM);
    float var  = ss * (1.f / DIM) - mean * mean;
    float rstd = rsqrtf(var + 1e-6f);
    orow[tid]       = __float2half((v0 - mean) * rstd * g[tid]       + b[tid]);
    orow[tid + 256] = __float2half((v1 - mean) * rstd * g[tid + 256] + b[tid + 256]);
    orow[tid + 512] = __float2half((v2 - mean) * rstd * g[tid + 512] + b[tid + 512]);
}

__global__ __launch_bounds__(256) void ln2_kernel(
    const float* __restrict__ xin, const float* __restrict__ g,
    const float* __restrict__ b, __half* __restrict__ out)
{
    int t = blockIdx.x;
    const float* row = xin + (size_t)t * DIM;
    __half* orow = out + (size_t)t * DIM;
    int tid = threadIdx.x;
    float v0 = row[tid], v1 = row[tid + 256], v2 = row[tid + 512];
    float s = v0 + v1 + v2, ss = v0 * v0 + v1 * v1 + v2 * v2;
    blockReduce2(s, ss);
    float mean = s * (1.f / DIM);
    float var  = ss * (1.f / DIM) - mean * mean;
    float rstd = rsqrtf(var + 1e-6f);
    orow[tid]       = __float2half((v0 - mean) * rstd * g[tid]       + b[tid]);
    orow[tid + 256] = __float2half((v1 - mean) * rstd * g[tid + 256] + b[tid + 256]);
    orow[tid + 512] = __float2half((v2 - mean) * rstd * g[tid + 512] + b[tid + 512]);
}

// -------------------- weight transpose fp32 -> half --------------------------
__global__ __launch_bounds__(256) void transpose_h(
    const float* __restrict__ in, __half* __restrict__ out, int R, int C)
{
    __shared__ float t[32][33];
    int bx = blockIdx.x << 5, by = blockIdx.y << 5;
    int lx = threadIdx.x, ly = threadIdx.y;
    #pragma unroll
    for (int j = 0; j < 4; j++) {
        int r = by + ly + j * 8, c = bx + lx;
        if (r < R && c < C) t[ly + j * 8][lx] = in[(size_t)r * C + c];
    }
    __syncthreads();
    #pragma unroll
    for (int j = 0; j < 4; j++) {
        int oc = by + lx, orr = bx + ly + j * 8;
        if (orr < C && oc < R) out[(size_t)orr * R + oc] = __float2half(t[lx][ly + j * 8]);
    }
}

// -------------------- fp16 tensor-core GEMM, k=32 tiles, 4-stage cp.async ----
// C[m,n] = A[m,:] @ Bt[n,:]^T + bias[n] (+gelu)(+res). 128x128 CTA tile,
// 8 warps (64x32), mma.m16n8k16.f16, A and B via ldmatrix.
#define RSTR 80                     // smem row stride bytes (32 halves + 16B pad)
#define ASTG (128 * RSTR)           // 10240 B per A stage
#define STG2 (2 * ASTG)             // A+B per stage
#define STAGES 4
#define GEMM_SMEM (STAGES * STG2)   // 81920 B

template<bool GATHER, bool GELU_ACT, bool RES, bool HALF_OUT>
__global__ __launch_bounds__(256, 2) void gemm_h(
    const __half* __restrict__ A, const __half* __restrict__ Bt,
    const float* __restrict__ bias, const float* __restrict__ Rs,
    void* __restrict__ Cv, int M, int Nn, int K)
{
    extern __shared__ char smc[];
    const int tid  = threadIdx.x;
    const int lane = tid & 31;
    const int warp = tid >> 5;
    const int wm = warp >> 2;
    const int wn = warp & 3;
    const int bm = blockIdx.y << 7;
    const int bn = blockIdx.x << 7;
    const int KT = K >> 5;

    // ---- load assignments: row = tid>>1, 32B chunk = tid&1 ----
    const int lrow = tid >> 1;
    const int lch  = tid & 1;
    int gm = bm + lrow;
    int arow = gm < M ? gm : M - 1;
    if (GATHER) {
        int img = arow >> 12, rem = arow & 4095;
        int y = rem >> 6, xc = rem & 63;
        arow = (img * 25 + (y / WIN) * 5 + (xc / WIN)) * NTOK
             + (y % WIN) * WIN + (xc % WIN);
    }
    const __half* srcA = A  + (size_t)arow * K + lch * 16;
    const __half* srcB = Bt + (size_t)(bn + lrow) * K + lch * 16;
    char* dA = smc + lrow * RSTR + lch * 32;
    char* dB = dA + ASTG;

    auto issue = [&](int kt, int s) {
        char* a = dA + s * STG2;
        char* b = dB + s * STG2;
        const __half* sa = srcA + kt * 32;
        const __half* sb = srcB + kt * 32;
        cp16(a, sa); cp16(a + 16, sa + 8);
        cp16(b, sb); cp16(b + 16, sb + 8);
    };

    // ---- fragment addressing ----
    uint32_t base0 = (uint32_t)__cvta_generic_to_shared(smc);
    const int l16 = lane & 15;
    const int lh  = lane >> 4;          // 0/1 -> 8-half column group
    const uint32_t aoff = (uint32_t)((wm * 64 + l16) * RSTR + lh * 16);
    const uint32_t boff = (uint32_t)(ASTG + (wn * 32 + l16) * RSTR + lh * 16);

    float acc[4][4][4];
    #pragma unroll
    for (int i = 0; i < 4; i++)
        #pragma unroll
        for (int j = 0; j < 4; j++)
            #pragma unroll
            for (int c = 0; c < 4; c++) acc[i][j][c] = 0.f;

    // ---- prologue ----
    issue(0, 0); CP_COMMIT();
    issue(1, 1); CP_COMMIT();
    issue(2, 2); CP_COMMIT();

    for (int kt = 0; kt < KT; kt++) {
        CP_WAIT2();
        __syncthreads();
        {
            int nk = kt + 3;
            if (nk < KT) issue(nk, nk & 3);
            CP_COMMIT();
        }

        uint32_t sb = base0 + (uint32_t)((kt & 3) * STG2);
        #pragma unroll
        for (int kh = 0; kh < 2; kh++) {
            uint32_t kb = (uint32_t)(kh * 32);
            uint32_t a[4][4], bw[2][4];
            #pragma unroll
            for (int mt = 0; mt < 4; mt++) {
                uint32_t ad = sb + aoff + (uint32_t)(mt * 16 * RSTR) + kb;
                asm volatile("ldmatrix.sync.aligned.m8n8.x4.shared.b16 {%0,%1,%2,%3}, [%4];"
                    : "=r"(a[mt][0]), "=r"(a[mt][1]), "=r"(a[mt][2]), "=r"(a[mt][3])
                    : "r"(ad));
            }
            #pragma unroll
            for (int g = 0; g < 2; g++) {
                uint32_t bd = sb + boff + (uint32_t)(g * 16 * RSTR) + kb;
                asm volatile("ldmatrix.sync.aligned.m8n8.x4.shared.b16 {%0,%1,%2,%3}, [%4];"
                    : "=r"(bw[g][0]), "=r"(bw[g][1]), "=r"(bw[g][2]), "=r"(bw[g][3])
                    : "r"(bd));
            }
            #pragma unroll
            for (int mt = 0; mt < 4; mt++)
                #pragma unroll
                for (int nt = 0; nt < 4; nt++) {
                    int g = nt >> 1, t = nt & 1;
                    asm volatile(
                        "mma.sync.aligned.m16n8k16.row.col.f32.f16.f16.f32 "
                        "{%0,%1,%2,%3}, {%4,%5,%6,%7}, {%8,%9}, {%0,%1,%2,%3};"
                        : "+f"(acc[mt][nt][0]), "+f"(acc[mt][nt][1]),
                          "+f"(acc[mt][nt][2]), "+f"(acc[mt][nt][3])
                        : "r"(a[mt][0]), "r"(a[mt][1]), "r"(a[mt][2]), "r"(a[mt][3]),
                          "r"(bw[g][t]), "r"(bw[g][t + 2]));
                }
        }
    }

    // ---- epilogue ----
    const int rbase = bm + wm * 64 + (lane >> 2);
    const int cbase = bn + wn * 32 + (lane & 3) * 2;
    float* Cf = (float*)Cv;
    __half* Ch = (__half*)Cv;
    #pragma unroll
    for (int nt = 0; nt < 4; nt++) {
        int col = cbase + nt * 8;
        float bs0 = bias[col], bs1 = bias[col + 1];
        #pragma unroll
        for (int mt = 0; mt < 4; mt++) {
            int r0 = rbase + mt * 16;
            int r1 = r0 + 8;
            float v00 = acc[mt][nt][0] + bs0;
            float v01 = acc[mt][nt][1] + bs1;
            float v10 = acc[mt][nt][2] + bs0;
            float v11 = acc[mt][nt][3] + bs1;
            if (GELU_ACT) {
                v00 = 0.5f * v00 * (1.f + erff(v00 * 0.70710678f));
                v01 = 0.5f * v01 * (1.f + erff(v01 * 0.70710678f));
                v10 = 0.5f * v10 * (1.f + erff(v10 * 0.70710678f));
                v11 = 0.5f * v11 * (1.f + erff(v11 * 0.70710678f));
            }
            if (r0 < M) {
                if (RES) {
                    const float* rr = Rs + (size_t)r0 * Nn + col;
                    v00 += rr[0]; v01 += rr[1];
                }
                if (HALF_OUT)
                    *(__half2*)(Ch + (size_t)r0 * Nn + col) =
                        __floats2half2_rn(v00, v01);
                else
                    *(float2*)(Cf + (size_t)r0 * Nn + col) = make_float2(v00, v01);
            }
            if (r1 < M) {
                if (RES) {
                    const float* rr = Rs + (size_t)r1 * Nn + col;
                    v10 += rr[0]; v11 += rr[1];
                }
                if (HALF_OUT)
                    *(__half2*)(Ch + (size_t)r1 * Nn + col) =
                        __floats2half2_rn(v10, v11);
                else
                    *(float2*)(Cf + (size_t)r1 * Nn + col) = make_float2(v10, v11);
            }
        }
    }
}

// -------------------- attention: one CTA per (window, head) ------------------
#define KV_STRIDE 68
#define SM_K   0
#define SM_V   (NTOK * KV_STRIDE)
#define SM_P   (2 * NTOK * KV_STRIDE)
#define SM_R   (SM_P + 8 * NTOK)
#define ATTN_SMEM_FLOATS (SM_R + 8 * 28)

__global__ __launch_bounds__(256) void attn_kernel(
    const float* __restrict__ qkv, const float* __restrict__ relh,
    const float* __restrict__ relw, __half* __restrict__ outp)
{
    extern __shared__ float sm[];
    float* Ks = sm + SM_K;
    float* Vs = sm + SM_V;

    const int blk = blockIdx.x;
    const int w = blk / HEADS, h = blk % HEADS;
    const float* base = qkv + (size_t)w * NTOK * QKVN;
    const int tid = threadIdx.x, warp = tid >> 5, lane = tid & 31;

    for (int idx = tid; idx < NTOK * HD; idx += 256) {
        int j = idx >> 6, d = idx & 63;
        const float* src = base + (size_t)j * QKVN + h * HD + d;
        Ks[j * KV_STRIDE + d] = src[DIM];
        Vs[j * KV_STRIDE + d] = src[2 * DIM];
    }
    __syncthreads();

    float* myp  = sm + SM_P + warp * NTOK;
    float* myrh = sm + SM_R + warp * 28;
    float* myrw = myrh + 14;

    for (int r = warp; r < NTOK; r += 8) {
        const float4* qsrc = (const float4*)(base + (size_t)r * QKVN + h * HD);
        float4 qv[16];
        #pragma unroll
        for (int d4 = 0; d4 < 16; d4++) qv[d4] = qsrc[d4];

        int ty = r / WIN, tx = r % WIN;
        if (lane < 28) {
            int kk = lane % 14;
            bool isw = lane >= 14;
            const float4* rp = (const float4*)(isw ? (relw + (size_t)(tx - kk + 13) * HD)
                                                   : (relh + (size_t)(ty - kk + 13) * HD));
            float s = 0.f;
            #pragma unroll
            for (int d4 = 0; d4 < 16; d4++) {
                float4 rv = rp[d4];
                s += qv[d4].x * rv.x + qv[d4].y * rv.y + qv[d4].z * rv.z + qv[d4].w * rv.w;
            }
            (isw ? myrw : myrh)[kk] = s;
        }
        __syncwarp();

        float sc[7];
        float mx = -INFINITY;
        #pragma unroll
        for (int i = 0; i < 7; i++) {
            int j = lane + i * 32;
            float s = -INFINITY;
            if (j < NTOK) {
                const float4* kr = (const float4*)(Ks + j * KV_STRIDE);
                float a = 0.f;
                #pragma unroll
                for (int d4 = 0; d4 < 16; d4++) {
                    float4 kv = kr[d4];
                    a += qv[d4].x * kv.x + qv[d4].y * kv.y + qv[d4].z * kv.z + qv[d4].w * kv.w;
                }
                s = a * SCALE + myrh[j / WIN] + myrw[j % WIN];
            }
            sc[i] = s;
            mx = fmaxf(mx, s);
        }
        #pragma unroll
        for (int o = 16; o; o >>= 1) mx = fmaxf(mx, __shfl_xor_sync(0xffffffffu, mx, o));
        float sum = 0.f;
        #pragma unroll
        for (int i = 0; i < 7; i++) {
            int j = lane + i * 32;
            if (j < NTOK) {
                float e = __expf(sc[i] - mx);
                sum += e;
                myp[j] = e;
            }
        }
        #pragma unroll
        for (int o = 16; o; o >>= 1) sum += __shfl_xor_sync(0xffffffffu, sum, o);
        float inv = 1.f / sum;
        __syncwarp();

        float2 acc = make_float2(0.f, 0.f);
        #pragma unroll 4
        for (int j = 0; j < NTOK; j++) {
            float p = myp[j];
            float2 vv = *(const float2*)(Vs + j * KV_STRIDE + lane * 2);
            acc.x += p * vv.x;
            acc.y += p * vv.y;
        }
        __half* orow = outp + ((size_t)w * NTOK + r) * DIM + h * HD;
        *(__half2*)(orow + lane * 2) = __floats2half2_rn(acc.x * inv, acc.y * inv);
        __syncwarp();
    }
}

// -------------------- launch -------------------------------------------------
extern "C" void kernel_launch(void* const* d_in, const int* in_sizes, int n_in,
                              void* d_out, int out_size)
{
    const float* x      = (const float*)d_in[0];
    const float* ln1_g  = (const float*)d_in[1];
    const float* ln1_b  = (const float*)d_in[2];
    const float* qkv_w  = (const float*)d_in[3];
    const float* qkv_b  = (const float*)d_in[4];
    const float* proj_w = (const float*)d_in[5];
    const float* proj_b = (const float*)d_in[6];
    const float* rel_h  = (const float*)d_in[7];
    const float* rel_w  = (const float*)d_in[8];
    const float* ln2_g  = (const float*)d_in[9];
    const float* ln2_b  = (const float*)d_in[10];
    const float* fc1_w  = (const float*)d_in[11];
    const float* fc1_b  = (const float*)d_in[12];
    const float* fc2_w  = (const float*)d_in[13];
    const float* fc2_b  = (const float*)d_in[14];
    float* out = (float*)d_out;

    __half *p_xin, *p_attn, *p_h2, *p_hid;
    __half *p_qkvT, *p_projT, *p_fc1T, *p_fc2T;
    float *p_qkv, *p_xres;
    cudaGetSymbolAddress((void**)&p_xin,  g_xin_h);
    cudaGetSymbolAddress((void**)&p_qkv,  g_qkv);
    cudaGetSymbolAddress((void**)&p_attn, g_attn_h);
    cudaGetSymbolAddress((void**)&p_xres, g_xres);
    cudaGetSymbolAddress((void**)&p_h2,   g_h2_h);
    cudaGetSymbolAddress((void**)&p_hid,  g_hid_h);
    cudaGetSymbolAddress((void**)&p_qkvT,  g_qkvwT);
    cudaGetSymbolAddress((void**)&p_projT, g_projwT);
    cudaGetSymbolAddress((void**)&p_fc1T,  g_fc1wT);
    cudaGetSymbolAddress((void**)&p_fc2T,  g_fc2wT);

    const int attn_smem = ATTN_SMEM_FLOATS * sizeof(float);
    cudaFuncSetAttribute(attn_kernel, cudaFuncAttributeMaxDynamicSharedMemorySize, attn_smem);
    cudaFuncSetAttribute((const void*)gemm_h<false, false, false, false>,
                         cudaFuncAttributeMaxDynamicSharedMemorySize, GEMM_SMEM);
    cudaFuncSetAttribute((const void*)gemm_h<true, false, true, false>,
                         cudaFuncAttributeMaxDynamicSharedMemorySize, GEMM_SMEM);
    cudaFuncSetAttribute((const void*)gemm_h<false, true, false, true>,
                         cudaFuncAttributeMaxDynamicSharedMemorySize, GEMM_SMEM);
    cudaFuncSetAttribute((const void*)gemm_h<false, false, true, false>,
                         cudaFuncAttributeMaxDynamicSharedMemorySize, GEMM_SMEM);

    dim3 tb(32, 8);
    transpose_h<<<dim3(QKVN / 32, DIM / 32), tb>>>(qkv_w,  p_qkvT,  DIM, QKVN);
    transpose_h<<<dim3(DIM / 32,  DIM / 32), tb>>>(proj_w, p_projT, DIM, DIM);
    transpose_h<<<dim3(MLPH / 32, DIM / 32), tb>>>(fc1_w,  p_fc1T,  DIM, MLPH);
    transpose_h<<<dim3(DIM / 32,  MLPH / 32), tb>>>(fc2_w, p_fc2T,  MLPH, DIM);

    // 1. LN1 + window partition (half out)
    ln1_kernel<<<MROWS, 256>>>(x, ln1_g, ln1_b, p_xin);

    // 2. QKV GEMM [9800,768]x[768,2304] -> fp32
    gemm_h<false, false, false, false><<<dim3(QKVN / 128, (MROWS + 127) / 128), 256, GEMM_SMEM>>>(
        p_xin, p_qkvT, qkv_b, nullptr, p_qkv, MROWS, QKVN, DIM);

    // 3. attention (half out)
    attn_kernel<<<NWIN * HEADS, 256, attn_smem>>>(p_qkv, rel_h, rel_w, p_attn);

    // 4. proj GEMM + gather + residual -> fp32 xres
    gemm_h<true, false, true, false><<<dim3(DIM / 128, GROWS / 128), 256, GEMM_SMEM>>>(
        p_attn, p_projT, proj_b, x, p_xres, GROWS, DIM, DIM);

    // 5. LN2 (half out)
    ln2_kernel<<<GROWS, 256>>>(p_xres, ln2_g, ln2_b, p_h2);

    // 6. fc1 + GELU (half out)
    gemm_h<false, true, false, true><<<dim3(MLPH / 128, GROWS / 128), 256, GEMM_SMEM>>>(
        p_h2, p_fc1T, fc1_b, nullptr, p_hid, GROWS, MLPH, DIM);

    // 7. fc2 + residual -> out (fp32)
    gemm_h<false, false, true, false><<<dim3(DIM / 128, GROWS / 128), 256, GEMM_SMEM>>>(
        p_hid, p_fc2T, fc2_b, p_xres, out, GROWS, DIM, MLPH);
}

// round 12
// speedup vs baseline: 1.8512x; 1.2149x over previous
#include <cuda_runtime.h>
#include <cuda_fp16.h>
#include <math.h>
#include <stdint.h>

#define DIM   768
#define HEADS 12
#define HD    64
#define WIN   14
#define NTOK  196
#define NWIN  50
#define MROWS 9800
#define GROWS 8192
#define MLPH  3072
#define QKVN  2304
#define SCALE 0.125f

// -------------------- scratch (device globals; no allocation) ----------------
__device__ __half g_xin_h [MROWS * DIM];    // LN1 out (half), window-partitioned
__device__ __half g_qkv_h [MROWS * QKVN];   // qkv (half)
__device__ __half g_attn_h[MROWS * DIM];    // attention out (half)
__device__ float  g_xres  [GROWS * DIM];    // x + proj (fp32 master)
__device__ __half g_h2_h  [GROWS * DIM];    // LN2 out (half)
__device__ __half g_hid_h [GROWS * MLPH];   // gelu(fc1) (half)
// transposed half weights, rebuilt every launch
__device__ __half g_qkvwT [QKVN * DIM];
__device__ __half g_projwT[DIM * DIM];
__device__ __half g_fc1wT [MLPH * DIM];
__device__ __half g_fc2wT [DIM * MLPH];

// -------------------- helpers ------------------------------------------------
__device__ __forceinline__ void cp16(void* dst, const void* src) {
    uint32_t d = (uint32_t)__cvta_generic_to_shared(dst);
    asm volatile("cp.async.cg.shared.global [%0], [%1], 16;\n" :: "r"(d), "l"(src));
}
#define CP_COMMIT()  asm volatile("cp.async.commit_group;\n")
#define CP_WAIT2()   asm volatile("cp.async.wait_group 2;\n")

// pack two fp32 -> one fp16x2 register (lo = first arg, hi = second arg)
__device__ __forceinline__ uint32_t packh2(float lo, float hi) {
    uint32_t r;
    asm("cvt.rn.f16x2.f32 %0, %1, %2;" : "=r"(r) : "f"(hi), "f"(lo));
    return r;
}

__device__ __forceinline__ void blockReduce2(float& s, float& ss) {
    #pragma unroll
    for (int o = 16; o; o >>= 1) {
        s  += __shfl_xor_sync(0xffffffffu, s,  o);
        ss += __shfl_xor_sync(0xffffffffu, ss, o);
    }
    __shared__ float ra[8], rb[8];
    int warp = threadIdx.x >> 5, lane = threadIdx.x & 31;
    if (lane == 0) { ra[warp] = s; rb[warp] = ss; }
    __syncthreads();
    if (threadIdx.x == 0) {
        float t1 = 0.f, t2 = 0.f;
        #pragma unroll
        for (int i = 0; i < 8; i++) { t1 += ra[i]; t2 += rb[i]; }
        ra[0] = t1; rb[0] = t2;
    }
    __syncthreads();
    s = ra[0]; ss = rb[0];
}

// -------------------- LN1 + window partition (half out) ----------------------
__global__ __launch_bounds__(256) void ln1_kernel(
    const float* __restrict__ x, const float* __restrict__ g,
    const float* __restrict__ b, __half* __restrict__ out)
{
    int t = blockIdx.x;
    int w  = t / NTOK, tk = t % NTOK;
    int img = w / 25, wy = (w % 25) / 5, wx = w % 5;
    int ty = tk / WIN, tx = tk % WIN;
    int y = wy * WIN + ty, xc = wx * WIN + tx;
    __half* orow = out + (size_t)t * DIM;
    int tid = threadIdx.x;
    if (y >= 64 || xc >= 64) {
        orow[tid] = __float2half(0.f);
        orow[tid + 256] = __float2half(0.f);
        orow[tid + 512] = __float2half(0.f);
        return;
    }
    const float* row = x + (((size_t)img * 64 + y) * 64 + xc) * DIM;
    float v0 = row[tid], v1 = row[tid + 256], v2 = row[tid + 512];
    float s = v0 + v1 + v2, ss = v0 * v0 + v1 * v1 + v2 * v2;
    blockReduce2(s, ss);
    float mean = s * (1.f / DIM);
    float var  = ss * (1.f / DIM) - mean * mean;
    float rstd = rsqrtf(var + 1e-6f);
    orow[tid]       = __float2half((v0 - mean) * rstd * g[tid]       + b[tid]);
    orow[tid + 256] = __float2half((v1 - mean) * rstd * g[tid + 256] + b[tid + 256]);
    orow[tid + 512] = __float2half((v2 - mean) * rstd * g[tid + 512] + b[tid + 512]);
}

__global__ __launch_bounds__(256) void ln2_kernel(
    const float* __restrict__ xin, const float* __restrict__ g,
    const float* __restrict__ b, __half* __restrict__ out)
{
    int t = blockIdx.x;
    const float* row = xin + (size_t)t * DIM;
    __half* orow = out + (size_t)t * DIM;
    int tid = threadIdx.x;
    float v0 = row[tid], v1 = row[tid + 256], v2 = row[tid + 512];
    float s = v0 + v1 + v2, ss = v0 * v0 + v1 * v1 + v2 * v2;
    blockReduce2(s, ss);
    float mean = s * (1.f / DIM);
    float var  = ss * (1.f / DIM) - mean * mean;
    float rstd = rsqrtf(var + 1e-6f);
    orow[tid]       = __float2half((v0 - mean) * rstd * g[tid]       + b[tid]);
    orow[tid + 256] = __float2half((v1 - mean) * rstd * g[tid + 256] + b[tid + 256]);
    orow[tid + 512] = __float2half((v2 - mean) * rstd * g[tid + 512] + b[tid + 512]);
}

// -------------------- weight transpose fp32 -> half --------------------------
__global__ __launch_bounds__(256) void transpose_h(
    const float* __restrict__ in, __half* __restrict__ out, int R, int C)
{
    __shared__ float t[32][33];
    int bx = blockIdx.x << 5, by = blockIdx.y << 5;
    int lx = threadIdx.x, ly = threadIdx.y;
    #pragma unroll
    for (int j = 0; j < 4; j++) {
        int r = by + ly + j * 8, c = bx + lx;
        if (r < R && c < C) t[ly + j * 8][lx] = in[(size_t)r * C + c];
    }
    __syncthreads();
    #pragma unroll
    for (int j = 0; j < 4; j++) {
        int oc = by + lx, orr = bx + ly + j * 8;
        if (orr < C && oc < R) out[(size_t)orr * R + oc] = __float2half(t[lx][ly + j * 8]);
    }
}

// -------------------- fp16 tensor-core GEMM, k=32 tiles, 4-stage cp.async ----
#define RSTR 80
#define ASTG (128 * RSTR)
#define STG2 (2 * ASTG)
#define STAGES 4
#define GEMM_SMEM (STAGES * STG2)

template<bool GATHER, bool GELU_ACT, bool RES, bool HALF_OUT>
__global__ __launch_bounds__(256, 2) void gemm_h(
    const __half* __restrict__ A, const __half* __restrict__ Bt,
    const float* __restrict__ bias, const float* __restrict__ Rs,
    void* __restrict__ Cv, int M, int Nn, int K)
{
    extern __shared__ char smc[];
    const int tid  = threadIdx.x;
    const int lane = tid & 31;
    const int warp = tid >> 5;
    const int wm = warp >> 2;
    const int wn = warp & 3;
    const int bm = blockIdx.y << 7;
    const int bn = blockIdx.x << 7;
    const int KT = K >> 5;

    const int lrow = tid >> 1;
    const int lch  = tid & 1;
    int gm = bm + lrow;
    int arow = gm < M ? gm : M - 1;
    if (GATHER) {
        int img = arow >> 12, rem = arow & 4095;
        int y = rem >> 6, xc = rem & 63;
        arow = (img * 25 + (y / WIN) * 5 + (xc / WIN)) * NTOK
             + (y % WIN) * WIN + (xc % WIN);
    }
    const __half* srcA = A  + (size_t)arow * K + lch * 16;
    const __half* srcB = Bt + (size_t)(bn + lrow) * K + lch * 16;
    char* dA = smc + lrow * RSTR + lch * 32;
    char* dB = dA + ASTG;

    auto issue = [&](int kt, int s) {
        char* a = dA + s * STG2;
        char* b = dB + s * STG2;
        const __half* sa = srcA + kt * 32;
        const __half* sb = srcB + kt * 32;
        cp16(a, sa); cp16(a + 16, sa + 8);
        cp16(b, sb); cp16(b + 16, sb + 8);
    };

    uint32_t base0 = (uint32_t)__cvta_generic_to_shared(smc);
    const int l16 = lane & 15;
    const int lh  = lane >> 4;
    const uint32_t aoff = (uint32_t)((wm * 64 + l16) * RSTR + lh * 16);
    const uint32_t boff = (uint32_t)(ASTG + (wn * 32 + l16) * RSTR + lh * 16);

    float acc[4][4][4];
    #pragma unroll
    for (int i = 0; i < 4; i++)
        #pragma unroll
        for (int j = 0; j < 4; j++)
            #pragma unroll
            for (int c = 0; c < 4; c++) acc[i][j][c] = 0.f;

    issue(0, 0); CP_COMMIT();
    issue(1, 1); CP_COMMIT();
    issue(2, 2); CP_COMMIT();

    for (int kt = 0; kt < KT; kt++) {
        CP_WAIT2();
        __syncthreads();
        {
            int nk = kt + 3;
            if (nk < KT) issue(nk, nk & 3);
            CP_COMMIT();
        }

        uint32_t sb = base0 + (uint32_t)((kt & 3) * STG2);
        #pragma unroll
        for (int kh = 0; kh < 2; kh++) {
            uint32_t kb = (uint32_t)(kh * 32);
            uint32_t a[4][4], bw[2][4];
            #pragma unroll
            for (int mt = 0; mt < 4; mt++) {
                uint32_t ad = sb + aoff + (uint32_t)(mt * 16 * RSTR) + kb;
                asm volatile("ldmatrix.sync.aligned.m8n8.x4.shared.b16 {%0,%1,%2,%3}, [%4];"
                    : "=r"(a[mt][0]), "=r"(a[mt][1]), "=r"(a[mt][2]), "=r"(a[mt][3])
                    : "r"(ad));
            }
            #pragma unroll
            for (int g = 0; g < 2; g++) {
                uint32_t bd = sb + boff + (uint32_t)(g * 16 * RSTR) + kb;
                asm volatile("ldmatrix.sync.aligned.m8n8.x4.shared.b16 {%0,%1,%2,%3}, [%4];"
                    : "=r"(bw[g][0]), "=r"(bw[g][1]), "=r"(bw[g][2]), "=r"(bw[g][3])
                    : "r"(bd));
            }
            #pragma unroll
            for (int mt = 0; mt < 4; mt++)
                #pragma unroll
                for (int nt = 0; nt < 4; nt++) {
                    int g = nt >> 1, t = nt & 1;
                    asm volatile(
                        "mma.sync.aligned.m16n8k16.row.col.f32.f16.f16.f32 "
                        "{%0,%1,%2,%3}, {%4,%5,%6,%7}, {%8,%9}, {%0,%1,%2,%3};"
                        : "+f"(acc[mt][nt][0]), "+f"(acc[mt][nt][1]),
                          "+f"(acc[mt][nt][2]), "+f"(acc[mt][nt][3])
                        : "r"(a[mt][0]), "r"(a[mt][1]), "r"(a[mt][2]), "r"(a[mt][3]),
                          "r"(bw[g][t]), "r"(bw[g][t + 2]));
                }
        }
    }

    const int rbase = bm + wm * 64 + (lane >> 2);
    const int cbase = bn + wn * 32 + (lane & 3) * 2;
    float* Cf = (float*)Cv;
    __half* Ch = (__half*)Cv;
    #pragma unroll
    for (int nt = 0; nt < 4; nt++) {
        int col = cbase + nt * 8;
        float bs0 = bias[col], bs1 = bias[col + 1];
        #pragma unroll
        for (int mt = 0; mt < 4; mt++) {
            int r0 = rbase + mt * 16;
            int r1 = r0 + 8;
            float v00 = acc[mt][nt][0] + bs0;
            float v01 = acc[mt][nt][1] + bs1;
            float v10 = acc[mt][nt][2] + bs0;
            float v11 = acc[mt][nt][3] + bs1;
            if (GELU_ACT) {
                v00 = 0.5f * v00 * (1.f + erff(v00 * 0.70710678f));
                v01 = 0.5f * v01 * (1.f + erff(v01 * 0.70710678f));
                v10 = 0.5f * v10 * (1.f + erff(v10 * 0.70710678f));
                v11 = 0.5f * v11 * (1.f + erff(v11 * 0.70710678f));
            }
            if (r0 < M) {
                if (RES) {
                    const float* rr = Rs + (size_t)r0 * Nn + col;
                    v00 += rr[0]; v01 += rr[1];
                }
                if (HALF_OUT)
                    *(uint32_t*)(Ch + (size_t)r0 * Nn + col) = packh2(v00, v01);
                else
                    *(float2*)(Cf + (size_t)r0 * Nn + col) = make_float2(v00, v01);
            }
            if (r1 < M) {
                if (RES) {
                    const float* rr = Rs + (size_t)r1 * Nn + col;
                    v10 += rr[0]; v11 += rr[1];
                }
                if (HALF_OUT)
                    *(uint32_t*)(Ch + (size_t)r1 * Nn + col) = packh2(v10, v11);
                else
                    *(float2*)(Cf + (size_t)r1 * Nn + col) = make_float2(v10, v11);
            }
        }
    }
}

// -------------------- mma attention: one CTA per (window, head) --------------
// smem: Q/K/V half [208][72], rel tables fp32 [208][14] x2
#define ATT_STR   144              // bytes per row (72 halves)
#define ATT_Q     0
#define ATT_K     29952
#define ATT_V     59904
#define ATT_RH    89856
#define ATT_RW    101504
#define ATT_SMEM  113152

__global__ __launch_bounds__(256, 1) void attn_mma(
    const __half* __restrict__ qkv, const float* __restrict__ relh,
    const float* __restrict__ relw, __half* __restrict__ outp)
{
    extern __shared__ char smb[];
    uint32_t sbase = (uint32_t)__cvta_generic_to_shared(smb);
    float* rh = (float*)(smb + ATT_RH);
    float* rw = (float*)(smb + ATT_RW);

    const int blk = blockIdx.x;
    const int w = blk / HEADS, h = blk % HEADS;
    const int tid = threadIdx.x, lane = tid & 31, warp = tid >> 5;

    // ---- fill Q/K/V smem ----
    const __half* qbase = qkv + (size_t)w * NTOK * QKVN + h * HD;
    for (int idx = tid; idx < 196 * 8 * 3; idx += 256) {
        int mat = idx / (196 * 8);
        int rem = idx - mat * (196 * 8);
        int j = rem >> 3, c = rem & 7;
        const uint4* src = (const uint4*)(qbase + (size_t)j * QKVN + mat * DIM + c * 8);
        *(uint4*)(smb + mat * 29952 + j * ATT_STR + c * 16) = *src;
    }
    for (int idx = tid; idx < 12 * 9 * 3; idx += 256) {
        int mat = idx / (12 * 9);
        int rem = idx - mat * (12 * 9);
        int j = 196 + rem / 9, c = rem % 9;
        *(uint4*)(smb + mat * 29952 + j * ATT_STR + c * 16) = make_uint4(0, 0, 0, 0);
    }
    __syncthreads();

    // ---- rel tables: rh[i][k] = q_i . relh[i/14 - k + 13], rw with i%14 ----
    for (int idx = tid; idx < 2 * 196 * 14; idx += 256) {
        int sel = idx / (196 * 14);
        int rem = idx - sel * (196 * 14);
        int i = rem / 14, k = rem - i * 14;
        int coord = (sel ? (i % 14) : (i / 14)) - k + 13;
        const float2* tab = (const float2*)((sel ? relw : relh) + coord * HD);
        const __half2* qrow = (const __half2*)(smb + ATT_Q + i * ATT_STR);
        float s = 0.f;
        #pragma unroll 8
        for (int d2 = 0; d2 < 32; d2++) {
            float2 qq = __half22float2(qrow[d2]);
            float2 tv = tab[d2];
            s += qq.x * tv.x + qq.y * tv.y;
        }
        (sel ? rw : rh)[i * 14 + k] = s;
    }
    for (int idx = tid; idx < 2 * 12 * 14; idx += 256) {
        int sel = idx / (12 * 14);
        int rem = idx - sel * (12 * 14);
        (sel ? rw : rh)[(196 + rem / 14) * 14 + rem % 14] = 0.f;
    }
    __syncthreads();

    const int g = lane >> 2, qt = lane & 3;
    const int l8 = lane & 7;
    const int sel8 = (lane >> 3) & 1;

    for (int mt = warp; mt < 13; mt += 8) {
        // ---- Q fragments (4 k-steps) ----
        uint32_t qf[4][4];
        #pragma unroll
        for (int ks = 0; ks < 4; ks++) {
            uint32_t ad = sbase + ATT_Q + (uint32_t)((mt * 16 + (lane & 15)) * ATT_STR
                        + ks * 32 + (lane >> 4) * 16);
            asm volatile("ldmatrix.sync.aligned.m8n8.x4.shared.b16 {%0,%1,%2,%3}, [%4];"
                : "=r"(qf[ks][0]), "=r"(qf[ks][1]), "=r"(qf[ks][2]), "=r"(qf[ks][3])
                : "r"(ad));
        }

        // ---- S = Q K^T over 26 n-tiles ----
        float S[26][4];
        const int i0 = mt * 16 + g, i1 = i0 + 8;
        #pragma unroll
        for (int nt = 0; nt < 26; nt++) {
            float s0 = 0.f, s1 = 0.f, s2 = 0.f, s3 = 0.f;
            #pragma unroll
            for (int ks = 0; ks < 4; ks++) {
                uint32_t kd = sbase + ATT_K + (uint32_t)((nt * 8 + l8) * ATT_STR
                            + ks * 32 + sel8 * 16);
                uint32_t b0, b1;
                asm volatile("ldmatrix.sync.aligned.m8n8.x2.shared.b16 {%0,%1}, [%2];"
                    : "=r"(b0), "=r"(b1) : "r"(kd));
                asm volatile(
                    "mma.sync.aligned.m16n8k16.row.col.f32.f16.f16.f32 "
                    "{%0,%1,%2,%3}, {%4,%5,%6,%7}, {%8,%9}, {%0,%1,%2,%3};"
                    : "+f"(s0), "+f"(s1), "+f"(s2), "+f"(s3)
                    : "r"(qf[ks][0]), "r"(qf[ks][1]), "r"(qf[ks][2]), "r"(qf[ks][3]),
                      "r"(b0), "r"(b1));
            }
            int j0 = nt * 8 + 2 * qt, j1 = j0 + 1;
            int jh0 = (j0 * 4682) >> 16, jw0 = j0 - 14 * jh0;
            int jh1 = (j1 * 4682) >> 16, jw1 = j1 - 14 * jh1;
            S[nt][0] = (j0 < 196) ? s0 * SCALE + rh[i0 * 14 + jh0] + rw[i0 * 14 + jw0] : -1e30f;
            S[nt][1] = (j1 < 196) ? s1 * SCALE + rh[i0 * 14 + jh1] + rw[i0 * 14 + jw1] : -1e30f;
            S[nt][2] = (j0 < 196) ? s2 * SCALE + rh[i1 * 14 + jh0] + rw[i1 * 14 + jw0] : -1e30f;
            S[nt][3] = (j1 < 196) ? s3 * SCALE + rh[i1 * 14 + jh1] + rw[i1 * 14 + jw1] : -1e30f;
        }

        // ---- softmax (rows i0, i1) ----
        float mx0 = -1e30f, mx1 = -1e30f;
        #pragma unroll
        for (int nt = 0; nt < 26; nt++) {
            mx0 = fmaxf(mx0, fmaxf(S[nt][0], S[nt][1]));
            mx1 = fmaxf(mx1, fmaxf(S[nt][2], S[nt][3]));
        }
        mx0 = fmaxf(mx0, __shfl_xor_sync(0xffffffffu, mx0, 1));
        mx0 = fmaxf(mx0, __shfl_xor_sync(0xffffffffu, mx0, 2));
        mx1 = fmaxf(mx1, __shfl_xor_sync(0xffffffffu, mx1, 1));
        mx1 = fmaxf(mx1, __shfl_xor_sync(0xffffffffu, mx1, 2));
        float sum0 = 0.f, sum1 = 0.f;
        #pragma unroll
        for (int nt = 0; nt < 26; nt++) {
            S[nt][0] = __expf(S[nt][0] - mx0); sum0 += S[nt][0];
            S[nt][1] = __expf(S[nt][1] - mx0); sum0 += S[nt][1];
            S[nt][2] = __expf(S[nt][2] - mx1); sum1 += S[nt][2];
            S[nt][3] = __expf(S[nt][3] - mx1); sum1 += S[nt][3];
        }
        sum0 += __shfl_xor_sync(0xffffffffu, sum0, 1);
        sum0 += __shfl_xor_sync(0xffffffffu, sum0, 2);
        sum1 += __shfl_xor_sync(0xffffffffu, sum1, 1);
        sum1 += __shfl_xor_sync(0xffffffffu, sum1, 2);

        // ---- O = P V ----
        float O[8][4];
        #pragma unroll
        for (int nt = 0; nt < 8; nt++)
            #pragma unroll
            for (int c = 0; c < 4; c++) O[nt][c] = 0.f;

        #pragma unroll
        for (int kc = 0; kc < 13; kc++) {
            uint32_t p0 = packh2(S[2*kc][0],   S[2*kc][1]);
            uint32_t p1 = packh2(S[2*kc][2],   S[2*kc][3]);
            uint32_t p2 = packh2(S[2*kc+1][0], S[2*kc+1][1]);
            uint32_t p3 = packh2(S[2*kc+1][2], S[2*kc+1][3]);
            #pragma unroll
            for (int nt = 0; nt < 8; nt++) {
                uint32_t vd = sbase + ATT_V + (uint32_t)((kc * 16 + sel8 * 8 + l8) * ATT_STR
                            + nt * 16);
                uint32_t v0, v1;
                asm volatile("ldmatrix.sync.aligned.m8n8.x2.trans.shared.b16 {%0,%1}, [%2];"
                    : "=r"(v0), "=r"(v1) : "r"(vd));
                asm volatile(
                    "mma.sync.aligned.m16n8k16.row.col.f32.f16.f16.f32 "
                    "{%0,%1,%2,%3}, {%4,%5,%6,%7}, {%8,%9}, {%0,%1,%2,%3};"
                    : "+f"(O[nt][0]), "+f"(O[nt][1]), "+f"(O[nt][2]), "+f"(O[nt][3])
                    : "r"(p0), "r"(p1), "r"(p2), "r"(p3), "r"(v0), "r"(v1));
            }
        }

        // ---- write out ----
        float inv0 = 1.f / sum0, inv1 = 1.f / sum1;
        if (i0 < 196) {
            __half* orow = outp + ((size_t)w * NTOK + i0) * DIM + h * HD;
            #pragma unroll
            for (int nt = 0; nt < 8; nt++)
                *(uint32_t*)(orow + nt * 8 + 2 * qt) =
                    packh2(O[nt][0] * inv0, O[nt][1] * inv0);
        }
        if (i1 < 196) {
            __half* orow = outp + ((size_t)w * NTOK + i1) * DIM + h * HD;
            #pragma unroll
            for (int nt = 0; nt < 8; nt++)
                *(uint32_t*)(orow + nt * 8 + 2 * qt) =
                    packh2(O[nt][2] * inv1, O[nt][3] * inv1);
        }
    }
}

// -------------------- launch -------------------------------------------------
extern "C" void kernel_launch(void* const* d_in, const int* in_sizes, int n_in,
                              void* d_out, int out_size)
{
    const float* x      = (const float*)d_in[0];
    const float* ln1_g  = (const float*)d_in[1];
    const float* ln1_b  = (const float*)d_in[2];
    const float* qkv_w  = (const float*)d_in[3];
    const float* qkv_b  = (const float*)d_in[4];
    const float* proj_w = (const float*)d_in[5];
    const float* proj_b = (const float*)d_in[6];
    const float* rel_h  = (const float*)d_in[7];
    const float* rel_w  = (const float*)d_in[8];
    const float* ln2_g  = (const float*)d_in[9];
    const float* ln2_b  = (const float*)d_in[10];
    const float* fc1_w  = (const float*)d_in[11];
    const float* fc1_b  = (const float*)d_in[12];
    const float* fc2_w  = (const float*)d_in[13];
    const float* fc2_b  = (const float*)d_in[14];
    float* out = (float*)d_out;

    __half *p_xin, *p_qkv, *p_attn, *p_h2, *p_hid;
    __half *p_qkvT, *p_projT, *p_fc1T, *p_fc2T;
    float *p_xres;
    cudaGetSymbolAddress((void**)&p_xin,  g_xin_h);
    cudaGetSymbolAddress((void**)&p_qkv,  g_qkv_h);
    cudaGetSymbolAddress((void**)&p_attn, g_attn_h);
    cudaGetSymbolAddress((void**)&p_xres, g_xres);
    cudaGetSymbolAddress((void**)&p_h2,   g_h2_h);
    cudaGetSymbolAddress((void**)&p_hid,  g_hid_h);
    cudaGetSymbolAddress((void**)&p_qkvT,  g_qkvwT);
    cudaGetSymbolAddress((void**)&p_projT, g_projwT);
    cudaGetSymbolAddress((void**)&p_fc1T,  g_fc1wT);
    cudaGetSymbolAddress((void**)&p_fc2T,  g_fc2wT);

    cudaFuncSetAttribute(attn_mma, cudaFuncAttributeMaxDynamicSharedMemorySize, ATT_SMEM);
    cudaFuncSetAttribute((const void*)gemm_h<false, false, false, true>,
                         cudaFuncAttributeMaxDynamicSharedMemorySize, GEMM_SMEM);
    cudaFuncSetAttribute((const void*)gemm_h<true, false, true, false>,
                         cudaFuncAttributeMaxDynamicSharedMemorySize, GEMM_SMEM);
    cudaFuncSetAttribute((const void*)gemm_h<false, true, false, true>,
                         cudaFuncAttributeMaxDynamicSharedMemorySize, GEMM_SMEM);
    cudaFuncSetAttribute((const void*)gemm_h<false, false, true, false>,
                         cudaFuncAttributeMaxDynamicSharedMemorySize, GEMM_SMEM);

    dim3 tb(32, 8);
    transpose_h<<<dim3(QKVN / 32, DIM / 32), tb>>>(qkv_w,  p_qkvT,  DIM, QKVN);
    transpose_h<<<dim3(DIM / 32,  DIM / 32), tb>>>(proj_w, p_projT, DIM, DIM);
    transpose_h<<<dim3(MLPH / 32, DIM / 32), tb>>>(fc1_w,  p_fc1T,  DIM, MLPH);
    transpose_h<<<dim3(DIM / 32,  MLPH / 32), tb>>>(fc2_w, p_fc2T,  MLPH, DIM);

    // 1. LN1 + window partition (half out)
    ln1_kernel<<<MROWS, 256>>>(x, ln1_g, ln1_b, p_xin);

    // 2. QKV GEMM -> half
    gemm_h<false, false, false, true><<<dim3(QKVN / 128, (MROWS + 127) / 128), 256, GEMM_SMEM>>>(
        p_xin, p_qkvT, qkv_b, nullptr, p_qkv, MROWS, QKVN, DIM);

    // 3. mma attention (half out)
    attn_mma<<<NWIN * HEADS, 256, ATT_SMEM>>>(p_qkv, rel_h, rel_w, p_attn);

    // 4. proj GEMM + gather + residual -> fp32 xres
    gemm_h<true, false, true, false><<<dim3(DIM / 128, GROWS / 128), 256, GEMM_SMEM>>>(
        p_attn, p_projT, proj_b, x, p_xres, GROWS, DIM, DIM);

    // 5. LN2 (half out)
    ln2_kernel<<<GROWS, 256>>>(p_xres, ln2_g, ln2_b, p_h2);

    // 6. fc1 + GELU (half out)
    gemm_h<false, true, false, true><<<dim3(MLPH / 128, GROWS / 128), 256, GEMM_SMEM>>>(
        p_h2, p_fc1T, fc1_b, nullptr, p_hid, GROWS, MLPH, DIM);

    // 7. fc2 + residual -> out (fp32)
    gemm_h<false, false, true, false><<<dim3(DIM / 128, GROWS / 128), 256, GEMM_SMEM>>>(
        p_hid, p_fc2T, fc2_b, p_xres, out, GROWS, DIM, MLPH);
}